// round 13
// baseline (speedup 1.0000x reference)
#include <cuda_runtime.h>
#include <cuda_bf16.h>
#include <cstdint>
#include <stdint.h>
#include <math.h>

#define D      128
#define TWO_D  256
#define MTILE  64
#define NTHREADS 256
#define MAXN   50000
#define MAXE   800000

// A image: 64 rows x 256 bf16, row stride 528 bytes (conflict-free LDSM)
#define A_STRIDE 528
#define A_IMG    (64 * A_STRIDE)      // 33792
#define SMEM_AHI 0
#define SMEM_ALO A_IMG
#define SMEM_TOTAL (2 * A_IMG)        // 67584 -> 2 CTAs/SM

// ---------------------------------------------------------------------------
// Device globals
// ---------------------------------------------------------------------------
__device__ int   g_base[MAXN + 1];    // per-block-local exclusive scan
__device__ int   g_cursor[MAXN];
__device__ int   g_csr[MAXE];
__device__ int   g_bsum[64];          // block offsets (exclusive)
// Pre-computed mma.sync B fragments (per-lane register images), hi/lo terms.
__device__ uint4 g_B1fh[8192];
__device__ uint4 g_B1fl[8192];
__device__ uint4 g_B2fh[4096];
__device__ uint4 g_B2fl[4096];

// ---------------------------------------------------------------------------
// helpers
// ---------------------------------------------------------------------------
__device__ __forceinline__ uint32_t smem_u32(const void* p) {
    uint32_t a;
    asm("{ .reg .u64 t; cvta.to.shared.u64 t, %1; cvt.u32.u64 %0, t; }" : "=r"(a) : "l"(p));
    return a;
}
__device__ __forceinline__ void ldsm4(uint32_t* r, uint32_t addr) {
    asm volatile("ldmatrix.sync.aligned.m8n8.x4.shared.b16 {%0,%1,%2,%3}, [%4];"
                 : "=r"(r[0]), "=r"(r[1]), "=r"(r[2]), "=r"(r[3]) : "r"(addr));
}
__device__ __forceinline__ void mma16816(float* d, const uint32_t* a, uint32_t b0, uint32_t b1) {
    asm volatile("mma.sync.aligned.m16n8k16.row.col.f32.bf16.bf16.f32 "
                 "{%0,%1,%2,%3}, {%4,%5,%6,%7}, {%8,%9}, {%0,%1,%2,%3};"
                 : "+f"(d[0]), "+f"(d[1]), "+f"(d[2]), "+f"(d[3])
                 : "r"(a[0]), "r"(a[1]), "r"(a[2]), "r"(a[3]), "r"(b0), "r"(b1));
}
__device__ __forceinline__ int a_off(int row, int k) {
    return row * A_STRIDE + ((k >> 3) << 4) + ((k & 7) << 1);
}
__device__ __forceinline__ void split_pair(char* hi_base, char* lo_base, int off,
                                           float v0, float v1) {
    __nv_bfloat16 h0 = __float2bfloat16(v0);
    __nv_bfloat16 h1 = __float2bfloat16(v1);
    __nv_bfloat16 l0 = __float2bfloat16(v0 - __bfloat162float(h0));
    __nv_bfloat16 l1 = __float2bfloat16(v1 - __bfloat162float(h1));
    *reinterpret_cast<__nv_bfloat162*>(hi_base + off) = __halves2bfloat162(h0, h1);
    *reinterpret_cast<__nv_bfloat162*>(lo_base + off) = __halves2bfloat162(l0, l1);
}
__device__ __forceinline__ uint32_t pack_hi(float a, float b) {
    __nv_bfloat162 v = __halves2bfloat162(__float2bfloat16(a), __float2bfloat16(b));
    return *reinterpret_cast<uint32_t*>(&v);
}
__device__ __forceinline__ uint32_t pack_lo(float a, float b) {
    __nv_bfloat16 ha = __float2bfloat16(a), hb = __float2bfloat16(b);
    __nv_bfloat162 v = __halves2bfloat162(__float2bfloat16(a - __bfloat162float(ha)),
                                          __float2bfloat16(b - __bfloat162float(hb)));
    return *reinterpret_cast<uint32_t*>(&v);
}

// ---------------------------------------------------------------------------
// Kernel A (merged): blocks [0,12) -> weight fragment prep
//                    blocks [12, 12+nb) -> per-block scan of degree
// ---------------------------------------------------------------------------
__global__ void prep_scan_kernel(const float* __restrict__ W1,
                                 const float* __restrict__ W2,
                                 const float* __restrict__ degree, int N) {
    const int tid = threadIdx.x;
    if (blockIdx.x < 12) {
        int idx = blockIdx.x * 1024 + tid;
        if (idx < 8192) {
            int lane = idx & 31, ng = (idx >> 5) & 15, ks = idx >> 9;
            int n0 = ng * 16 + (lane >> 2);
            int kb = ks * 16 + (lane & 3) * 2;
            float a0 = W1[(size_t)(kb)     * 256 + n0], a1 = W1[(size_t)(kb + 1) * 256 + n0];
            float a2 = W1[(size_t)(kb + 8) * 256 + n0], a3 = W1[(size_t)(kb + 9) * 256 + n0];
            float a4 = W1[(size_t)(kb)     * 256 + n0 + 8], a5 = W1[(size_t)(kb + 1) * 256 + n0 + 8];
            float a6 = W1[(size_t)(kb + 8) * 256 + n0 + 8], a7 = W1[(size_t)(kb + 9) * 256 + n0 + 8];
            g_B1fh[idx] = make_uint4(pack_hi(a0, a1), pack_hi(a2, a3), pack_hi(a4, a5), pack_hi(a6, a7));
            g_B1fl[idx] = make_uint4(pack_lo(a0, a1), pack_lo(a2, a3), pack_lo(a4, a5), pack_lo(a6, a7));
        } else if (idx < 12288) {
            int i2 = idx - 8192;
            int lane = i2 & 31, ng = (i2 >> 5) & 7, ks = i2 >> 8;
            int n0 = ng * 16 + (lane >> 2);
            int kb = ks * 16 + (lane & 3) * 2;
            float a0 = W2[(size_t)(kb)     * 128 + n0], a1 = W2[(size_t)(kb + 1) * 128 + n0];
            float a2 = W2[(size_t)(kb + 8) * 128 + n0], a3 = W2[(size_t)(kb + 9) * 128 + n0];
            float a4 = W2[(size_t)(kb)     * 128 + n0 + 8], a5 = W2[(size_t)(kb + 1) * 128 + n0 + 8];
            float a6 = W2[(size_t)(kb + 8) * 128 + n0 + 8], a7 = W2[(size_t)(kb + 9) * 128 + n0 + 8];
            g_B2fh[i2] = make_uint4(pack_hi(a0, a1), pack_hi(a2, a3), pack_hi(a4, a5), pack_hi(a6, a7));
            g_B2fl[i2] = make_uint4(pack_lo(a0, a1), pack_lo(a2, a3), pack_lo(a4, a5), pack_lo(a6, a7));
        }
        return;
    }
    __shared__ int warp_sums[32];
    const int bid = blockIdx.x - 12;
    const int lane = tid & 31, wid = tid >> 5;
    const int i = bid * 1024 + tid;
    int v = (i < N) ? (int)degree[i] : 0;
    int inc = v;
#pragma unroll
    for (int o = 1; o < 32; o <<= 1) {
        int t = __shfl_up_sync(0xffffffffu, inc, o);
        if (lane >= o) inc += t;
    }
    if (lane == 31) warp_sums[wid] = inc;
    __syncthreads();
    if (wid == 0) {
        int ws = warp_sums[lane];
#pragma unroll
        for (int o = 1; o < 32; o <<= 1) {
            int t = __shfl_up_sync(0xffffffffu, ws, o);
            if (lane >= o) ws += t;
        }
        warp_sums[lane] = ws;
    }
    __syncthreads();
    int excl = (wid > 0 ? warp_sums[wid - 1] : 0) + inc - v;
    if (i < N) { g_base[i] = excl; g_cursor[i] = 0; }
    if (tid == 1023) g_bsum[bid] = warp_sums[31];
}

// Kernel B: scan block sums (1 block, 64 threads, nb <= 64)
__global__ void scan2_kernel(int nb) {
    const int tid = threadIdx.x, lane = tid & 31, wid = tid >> 5;
    __shared__ int ws2[2];
    int v = (tid < nb) ? g_bsum[tid] : 0;
    int inc = v;
#pragma unroll
    for (int o = 1; o < 32; o <<= 1) {
        int t = __shfl_up_sync(0xffffffffu, inc, o);
        if (lane >= o) inc += t;
    }
    if (lane == 31) ws2[wid] = inc;
    __syncthreads();
    int excl = inc - v + (wid > 0 ? ws2[0] : 0);
    if (tid < nb) g_bsum[tid] = excl;
}

// Kernel C: CSR fill (adds block offset inline)
__global__ void fill_kernel(const int* __restrict__ esrc,
                            const int* __restrict__ edst, int E) {
    int e = blockIdx.x * blockDim.x + threadIdx.x;
    if (e >= E) return;
    int t = edst[e];
    int pos = g_base[t] + g_bsum[t >> 10] + atomicAdd(&g_cursor[t], 1);
    if (pos < MAXE) g_csr[pos] = esrc[e];
}

// ---------------------------------------------------------------------------
// Fused kernel: CSR-gather + LN(x) + LN(neighbor) -> split-bf16 mma GEMM1
//               -> GELU -> GEMM2 -> bias + residual.  2 CTAs/SM.
// GEMM inner loops: batch-load ALL fragments for a k-step (MLP 8), then issue
// MMAs term-major (hh block, hl block, lh block) so each accumulator's reuse
// distance is 16 MMAs instead of 1.
// ---------------------------------------------------------------------------
__global__ void __launch_bounds__(NTHREADS, 2)
fused_kernel(const float* __restrict__ x,
             const float* __restrict__ degree,
             const float* __restrict__ sn_g, const float* __restrict__ sn_b,
             const float* __restrict__ nn_g, const float* __restrict__ nn_b,
             const float* __restrict__ b1,  const float* __restrict__ b2,
             float* __restrict__ out, int N, int nrows) {
    extern __shared__ char sm[];
    const uint32_t smem_base = smem_u32(sm);
    char* Ahi = sm + SMEM_AHI;
    char* Alo = sm + SMEM_ALO;

    const int tid  = threadIdx.x;
    const int lane = tid & 31;
    const int warp = tid >> 5;
    const int wm   = warp & 1;
    const int wn   = warp >> 1;
    const int row0 = blockIdx.x * MTILE;
    const int g    = lane >> 3;
    const int lr   = lane & 7;

    // ---------------- Stage 1: gather + LayerNorms -> A images --------------
    {
        const float4 g1  = *reinterpret_cast<const float4*>(sn_g + lane * 4);
        const float4 be1 = *reinterpret_cast<const float4*>(sn_b + lane * 4);
        const float4 g2  = *reinterpret_cast<const float4*>(nn_g + lane * 4);
        const float4 be2 = *reinterpret_cast<const float4*>(nn_b + lane * 4);
        const int k0 = lane * 4;
#pragma unroll
        for (int rr = 0; rr < 8; rr++) {
            const int r    = warp * 8 + rr;
            const int grow = row0 + r;
            if (grow < nrows) {
                // ---- LN(x) ----
                float4 xv = *reinterpret_cast<const float4*>(x + (size_t)grow * D + k0);
                float sum  = xv.x + xv.y + xv.z + xv.w;
                float sumq = xv.x * xv.x + xv.y * xv.y + xv.z * xv.z + xv.w * xv.w;
#pragma unroll
                for (int o = 16; o > 0; o >>= 1) {
                    sum  += __shfl_xor_sync(0xffffffffu, sum, o);
                    sumq += __shfl_xor_sync(0xffffffffu, sumq, o);
                }
                float mn   = sum * (1.0f / 128.0f);
                float rstd = rsqrtf(sumq * (1.0f / 128.0f) - mn * mn + 1e-5f);
                split_pair(Ahi, Alo, a_off(r, k0),     (xv.x - mn) * rstd * g1.x + be1.x,
                                                       (xv.y - mn) * rstd * g1.y + be1.y);
                split_pair(Ahi, Alo, a_off(r, k0 + 2), (xv.z - mn) * rstd * g1.z + be1.z,
                                                       (xv.w - mn) * rstd * g1.w + be1.w);

                // ---- CSR gather of neighbors (4-wide unroll, 2 accumulators)
                int node = grow, boff = 0;
                if (grow >= N) { node = grow - N; boff = N; }
                const float dgf = degree[node];
                const int   deg = (int)dgf;
                const float inv = 1.0f / fmaxf(dgf, 1.0f);
                const int   bs  = g_base[node] + g_bsum[node >> 10];
                float4 nva = make_float4(0.f, 0.f, 0.f, 0.f);
                float4 nvb = make_float4(0.f, 0.f, 0.f, 0.f);
                int j = 0;
                for (; j + 4 <= deg; j += 4) {
                    int s0 = g_csr[bs + j],     s1 = g_csr[bs + j + 1];
                    int s2 = g_csr[bs + j + 2], s3 = g_csr[bs + j + 3];
                    const float4 v0 = *reinterpret_cast<const float4*>(
                        x + ((size_t)(boff + s0)) * D + k0);
                    const float4 v1 = *reinterpret_cast<const float4*>(
                        x + ((size_t)(boff + s1)) * D + k0);
                    const float4 v2 = *reinterpret_cast<const float4*>(
                        x + ((size_t)(boff + s2)) * D + k0);
                    const float4 v3 = *reinterpret_cast<const float4*>(
                        x + ((size_t)(boff + s3)) * D + k0);
                    nva.x += v0.x + v1.x; nva.y += v0.y + v1.y;
                    nva.z += v0.z + v1.z; nva.w += v0.w + v1.w;
                    nvb.x += v2.x + v3.x; nvb.y += v2.y + v3.y;
                    nvb.z += v2.z + v3.z; nvb.w += v2.w + v3.w;
                }
                for (; j < deg; j++) {
                    int s0 = g_csr[bs + j];
                    const float4 v0 = *reinterpret_cast<const float4*>(
                        x + ((size_t)(boff + s0)) * D + k0);
                    nva.x += v0.x; nva.y += v0.y; nva.z += v0.z; nva.w += v0.w;
                }
                float4 nv;
                nv.x = (nva.x + nvb.x) * inv;
                nv.y = (nva.y + nvb.y) * inv;
                nv.z = (nva.z + nvb.z) * inv;
                nv.w = (nva.w + nvb.w) * inv;

                // ---- LN(neighbor) ----
                sum  = nv.x + nv.y + nv.z + nv.w;
                sumq = nv.x * nv.x + nv.y * nv.y + nv.z * nv.z + nv.w * nv.w;
#pragma unroll
                for (int o = 16; o > 0; o >>= 1) {
                    sum  += __shfl_xor_sync(0xffffffffu, sum, o);
                    sumq += __shfl_xor_sync(0xffffffffu, sumq, o);
                }
                mn   = sum * (1.0f / 128.0f);
                rstd = rsqrtf(sumq * (1.0f / 128.0f) - mn * mn + 1e-5f);
                split_pair(Ahi, Alo, a_off(r, 128 + k0),     (nv.x - mn) * rstd * g2.x + be2.x,
                                                             (nv.y - mn) * rstd * g2.y + be2.y);
                split_pair(Ahi, Alo, a_off(r, 128 + k0 + 2), (nv.z - mn) * rstd * g2.z + be2.z,
                                                             (nv.w - mn) * rstd * g2.w + be2.w);
            } else {
                split_pair(Ahi, Alo, a_off(r, k0),           0.f, 0.f);
                split_pair(Ahi, Alo, a_off(r, k0 + 2),       0.f, 0.f);
                split_pair(Ahi, Alo, a_off(r, 128 + k0),     0.f, 0.f);
                split_pair(Ahi, Alo, a_off(r, 128 + k0 + 2), 0.f, 0.f);
            }
        }
    }
    __syncthreads();

    // ---------------- Stage 2: GEMM1 (64 x 256 x 256, 3 split terms) --------
    float acc[2][8][4];
#pragma unroll
    for (int i = 0; i < 2; i++)
#pragma unroll
        for (int j = 0; j < 8; j++)
#pragma unroll
            for (int r = 0; r < 4; r++) acc[i][j][r] = 0.f;

#pragma unroll 2
    for (int ks = 0; ks < 16; ks++) {
        const int kabs = ks * 16;
        // batch-load all fragments for this k-step (high MLP)
        uint4 fh[4], fl[4];
#pragma unroll
        for (int jj = 0; jj < 4; jj++) {
            const int fi = (ks * 16 + wn * 4 + jj) * 32 + lane;
            fh[jj] = g_B1fh[fi];
            fl[jj] = g_B1fl[fi];
        }
        uint32_t ahi[2][4], alo[2][4];
#pragma unroll
        for (int ti = 0; ti < 2; ti++) {
            int row = wm * 32 + ti * 16 + (g & 1) * 8 + lr;
            uint32_t off = row * A_STRIDE + (((kabs >> 3) + (g >> 1)) << 4);
            ldsm4(ahi[ti], smem_base + SMEM_AHI + off);
            ldsm4(alo[ti], smem_base + SMEM_ALO + off);
        }
        // term-major MMA issue: hh, hl, lh (reuse distance 16)
#pragma unroll
        for (int jj = 0; jj < 4; jj++)
#pragma unroll
            for (int ti = 0; ti < 2; ti++) {
                mma16816(acc[ti][2 * jj],     ahi[ti], fh[jj].x, fh[jj].y);
                mma16816(acc[ti][2 * jj + 1], ahi[ti], fh[jj].z, fh[jj].w);
            }
#pragma unroll
        for (int jj = 0; jj < 4; jj++)
#pragma unroll
            for (int ti = 0; ti < 2; ti++) {
                mma16816(acc[ti][2 * jj],     ahi[ti], fl[jj].x, fl[jj].y);
                mma16816(acc[ti][2 * jj + 1], ahi[ti], fl[jj].z, fl[jj].w);
            }
#pragma unroll
        for (int jj = 0; jj < 4; jj++)
#pragma unroll
            for (int ti = 0; ti < 2; ti++) {
                mma16816(acc[ti][2 * jj],     alo[ti], fh[jj].x, fh[jj].y);
                mma16816(acc[ti][2 * jj + 1], alo[ti], fh[jj].z, fh[jj].w);
            }
    }

    // ---------------- Stage 3: bias + GELU -> A2 images ---------------------
    __syncthreads();
#pragma unroll
    for (int tj = 0; tj < 8; tj++) {
        const int col = wn * 64 + tj * 8 + (lane & 3) * 2;
        const float2 bb = *reinterpret_cast<const float2*>(b1 + col);
#pragma unroll
        for (int ti = 0; ti < 2; ti++)
#pragma unroll
            for (int rp = 0; rp < 2; rp++) {
                int row = wm * 32 + ti * 16 + (lane >> 2) + rp * 8;
                float v0 = acc[ti][tj][rp * 2 + 0] + bb.x;
                float v1 = acc[ti][tj][rp * 2 + 1] + bb.y;
                v0 = 0.5f * v0 * (1.0f + erff(v0 * 0.70710678118654752f));
                v1 = 0.5f * v1 * (1.0f + erff(v1 * 0.70710678118654752f));
                split_pair(Ahi, Alo, a_off(row, col), v0, v1);
            }
    }
    __syncthreads();

    // ---------------- Stage 4: GEMM2 (64 x 128 x 256, 3 split terms) --------
    float c2[2][4][4];
#pragma unroll
    for (int i = 0; i < 2; i++)
#pragma unroll
        for (int j = 0; j < 4; j++)
#pragma unroll
            for (int r = 0; r < 4; r++) c2[i][j][r] = 0.f;

#pragma unroll 2
    for (int ks = 0; ks < 16; ks++) {
        const int kabs = ks * 16;
        uint4 fh[2], fl[2];
#pragma unroll
        for (int jj = 0; jj < 2; jj++) {
            const int fi = (ks * 8 + wn * 2 + jj) * 32 + lane;
            fh[jj] = g_B2fh[fi];
            fl[jj] = g_B2fl[fi];
        }
        uint32_t ahi[2][4], alo[2][4];
#pragma unroll
        for (int ti = 0; ti < 2; ti++) {
            int row = wm * 32 + ti * 16 + (g & 1) * 8 + lr;
            uint32_t off = row * A_STRIDE + (((kabs >> 3) + (g >> 1)) << 4);
            ldsm4(ahi[ti], smem_base + SMEM_AHI + off);
            ldsm4(alo[ti], smem_base + SMEM_ALO + off);
        }
#pragma unroll
        for (int jj = 0; jj < 2; jj++)
#pragma unroll
            for (int ti = 0; ti < 2; ti++) {
                mma16816(c2[ti][2 * jj],     ahi[ti], fh[jj].x, fh[jj].y);
                mma16816(c2[ti][2 * jj + 1], ahi[ti], fh[jj].z, fh[jj].w);
            }
#pragma unroll
        for (int jj = 0; jj < 2; jj++)
#pragma unroll
            for (int ti = 0; ti < 2; ti++) {
                mma16816(c2[ti][2 * jj],     ahi[ti], fl[jj].x, fl[jj].y);
                mma16816(c2[ti][2 * jj + 1], ahi[ti], fl[jj].z, fl[jj].w);
            }
#pragma unroll
        for (int jj = 0; jj < 2; jj++)
#pragma unroll
            for (int ti = 0; ti < 2; ti++) {
                mma16816(c2[ti][2 * jj],     alo[ti], fh[jj].x, fh[jj].y);
                mma16816(c2[ti][2 * jj + 1], alo[ti], fh[jj].z, fh[jj].w);
            }
    }

    // ---------------- Stage 5: bias + residual + store ----------------------
#pragma unroll
    for (int tj = 0; tj < 4; tj++) {
        const int col = wn * 32 + tj * 8 + (lane & 3) * 2;
        const float2 bb = *reinterpret_cast<const float2*>(b2 + col);
#pragma unroll
        for (int ti = 0; ti < 2; ti++)
#pragma unroll
            for (int rp = 0; rp < 2; rp++) {
                int row  = wm * 32 + ti * 16 + (lane >> 2) + rp * 8;
                int grow = row0 + row;
                if (grow < nrows) {
                    const float2 xv = *reinterpret_cast<const float2*>(x + (size_t)grow * D + col);
                    float2 o;
                    o.x = xv.x + c2[ti][tj][rp * 2 + 0] + bb.x;
                    o.y = xv.y + c2[ti][tj][rp * 2 + 1] + bb.y;
                    *reinterpret_cast<float2*>(out + (size_t)grow * D + col) = o;
                }
            }
    }
}

// ---------------------------------------------------------------------------
extern "C" void kernel_launch(void* const* d_in, const int* in_sizes, int n_in,
                              void* d_out, int out_size) {
    const float* x      = (const float*)d_in[0];
    const int*   esrc   = (const int*)  d_in[1];
    const int*   edst   = (const int*)  d_in[2];
    const float* degree = (const float*)d_in[3];
    const float* sn_g   = (const float*)d_in[4];
    const float* sn_b   = (const float*)d_in[5];
    const float* nn_g   = (const float*)d_in[6];
    const float* nn_b   = (const float*)d_in[7];
    const float* W1     = (const float*)d_in[8];
    const float* b1     = (const float*)d_in[9];
    const float* W2     = (const float*)d_in[10];
    const float* b2     = (const float*)d_in[11];

    const int E     = in_sizes[1];
    const int nrows = in_sizes[0] / D;   // B*N
    const int N     = in_sizes[3];
    const int nb    = (N + 1023) / 1024;

    prep_scan_kernel<<<12 + nb, 1024>>>(W1, W2, degree, N);
    scan2_kernel<<<1, 64>>>(nb);
    fill_kernel<<<(E + 255) / 256, 256>>>(esrc, edst, E);

    cudaFuncSetAttribute(fused_kernel, cudaFuncAttributeMaxDynamicSharedMemorySize, SMEM_TOTAL);
    fused_kernel<<<(nrows + MTILE - 1) / MTILE, NTHREADS, SMEM_TOTAL>>>(
        x, degree, sn_g, sn_b, nn_g, nn_b, b1, b2, (float*)d_out, N, nrows);
}

// round 14
// speedup vs baseline: 1.0161x; 1.0161x over previous
#include <cuda_runtime.h>
#include <cuda_bf16.h>
#include <cstdint>
#include <stdint.h>
#include <math.h>

#define D      128
#define TWO_D  256
#define MTILE  64
#define NTHREADS 256
#define MAXN   50000
#define MAXE   800000

// A image: 64 rows x 256 bf16, row stride 528 bytes (conflict-free LDSM)
#define A_STRIDE 528
#define A_IMG    (64 * A_STRIDE)      // 33792
#define SMEM_AHI 0
#define SMEM_ALO A_IMG
#define SMEM_TOTAL (2 * A_IMG)        // 67584 -> 2 CTAs/SM

// ---------------------------------------------------------------------------
// Device globals
// ---------------------------------------------------------------------------
__device__ int   g_base[MAXN + 1];    // per-block-local exclusive scan
__device__ int   g_cursor[MAXN];
__device__ int   g_csr[MAXE];
__device__ int   g_bsum[64];          // block offsets (exclusive)
// Pre-computed mma.sync B fragments (per-lane register images), hi/lo terms.
__device__ uint4 g_B1fh[8192];
__device__ uint4 g_B1fl[8192];
__device__ uint4 g_B2fh[4096];
__device__ uint4 g_B2fl[4096];

// ---------------------------------------------------------------------------
// helpers
// ---------------------------------------------------------------------------
__device__ __forceinline__ uint32_t smem_u32(const void* p) {
    uint32_t a;
    asm("{ .reg .u64 t; cvta.to.shared.u64 t, %1; cvt.u32.u64 %0, t; }" : "=r"(a) : "l"(p));
    return a;
}
__device__ __forceinline__ void ldsm4(uint32_t* r, uint32_t addr) {
    asm volatile("ldmatrix.sync.aligned.m8n8.x4.shared.b16 {%0,%1,%2,%3}, [%4];"
                 : "=r"(r[0]), "=r"(r[1]), "=r"(r[2]), "=r"(r[3]) : "r"(addr));
}
__device__ __forceinline__ void mma16816(float* d, const uint32_t* a, uint32_t b0, uint32_t b1) {
    asm volatile("mma.sync.aligned.m16n8k16.row.col.f32.bf16.bf16.f32 "
                 "{%0,%1,%2,%3}, {%4,%5,%6,%7}, {%8,%9}, {%0,%1,%2,%3};"
                 : "+f"(d[0]), "+f"(d[1]), "+f"(d[2]), "+f"(d[3])
                 : "r"(a[0]), "r"(a[1]), "r"(a[2]), "r"(a[3]), "r"(b0), "r"(b1));
}
// Half-CTA barrier: warps 0-3 -> barrier 1, warps 4-7 -> barrier 2 (128 threads each)
#define GROUP_BAR(grp) asm volatile("bar.sync %0, 128;" :: "r"(1 + (grp)) : "memory")

__device__ __forceinline__ int a_off(int row, int k) {
    return row * A_STRIDE + ((k >> 3) << 4) + ((k & 7) << 1);
}
__device__ __forceinline__ void split_pair(char* hi_base, char* lo_base, int off,
                                           float v0, float v1) {
    __nv_bfloat16 h0 = __float2bfloat16(v0);
    __nv_bfloat16 h1 = __float2bfloat16(v1);
    __nv_bfloat16 l0 = __float2bfloat16(v0 - __bfloat162float(h0));
    __nv_bfloat16 l1 = __float2bfloat16(v1 - __bfloat162float(h1));
    *reinterpret_cast<__nv_bfloat162*>(hi_base + off) = __halves2bfloat162(h0, h1);
    *reinterpret_cast<__nv_bfloat162*>(lo_base + off) = __halves2bfloat162(l0, l1);
}
__device__ __forceinline__ uint32_t pack_hi(float a, float b) {
    __nv_bfloat162 v = __halves2bfloat162(__float2bfloat16(a), __float2bfloat16(b));
    return *reinterpret_cast<uint32_t*>(&v);
}
__device__ __forceinline__ uint32_t pack_lo(float a, float b) {
    __nv_bfloat16 ha = __float2bfloat16(a), hb = __float2bfloat16(b);
    __nv_bfloat162 v = __halves2bfloat162(__float2bfloat16(a - __bfloat162float(ha)),
                                          __float2bfloat16(b - __bfloat162float(hb)));
    return *reinterpret_cast<uint32_t*>(&v);
}

// ---------------------------------------------------------------------------
// Kernel A (merged): blocks [0,12) -> weight fragment prep
//                    blocks [12, 12+nb) -> per-block scan of degree
// ---------------------------------------------------------------------------
__global__ void prep_scan_kernel(const float* __restrict__ W1,
                                 const float* __restrict__ W2,
                                 const float* __restrict__ degree, int N) {
    const int tid = threadIdx.x;
    if (blockIdx.x < 12) {
        int idx = blockIdx.x * 1024 + tid;
        if (idx < 8192) {
            int lane = idx & 31, ng = (idx >> 5) & 15, ks = idx >> 9;
            int n0 = ng * 16 + (lane >> 2);
            int kb = ks * 16 + (lane & 3) * 2;
            float a0 = W1[(size_t)(kb)     * 256 + n0], a1 = W1[(size_t)(kb + 1) * 256 + n0];
            float a2 = W1[(size_t)(kb + 8) * 256 + n0], a3 = W1[(size_t)(kb + 9) * 256 + n0];
            float a4 = W1[(size_t)(kb)     * 256 + n0 + 8], a5 = W1[(size_t)(kb + 1) * 256 + n0 + 8];
            float a6 = W1[(size_t)(kb + 8) * 256 + n0 + 8], a7 = W1[(size_t)(kb + 9) * 256 + n0 + 8];
            g_B1fh[idx] = make_uint4(pack_hi(a0, a1), pack_hi(a2, a3), pack_hi(a4, a5), pack_hi(a6, a7));
            g_B1fl[idx] = make_uint4(pack_lo(a0, a1), pack_lo(a2, a3), pack_lo(a4, a5), pack_lo(a6, a7));
        } else if (idx < 12288) {
            int i2 = idx - 8192;
            int lane = i2 & 31, ng = (i2 >> 5) & 7, ks = i2 >> 8;
            int n0 = ng * 16 + (lane >> 2);
            int kb = ks * 16 + (lane & 3) * 2;
            float a0 = W2[(size_t)(kb)     * 128 + n0], a1 = W2[(size_t)(kb + 1) * 128 + n0];
            float a2 = W2[(size_t)(kb + 8) * 128 + n0], a3 = W2[(size_t)(kb + 9) * 128 + n0];
            float a4 = W2[(size_t)(kb)     * 128 + n0 + 8], a5 = W2[(size_t)(kb + 1) * 128 + n0 + 8];
            float a6 = W2[(size_t)(kb + 8) * 128 + n0 + 8], a7 = W2[(size_t)(kb + 9) * 128 + n0 + 8];
            g_B2fh[i2] = make_uint4(pack_hi(a0, a1), pack_hi(a2, a3), pack_hi(a4, a5), pack_hi(a6, a7));
            g_B2fl[i2] = make_uint4(pack_lo(a0, a1), pack_lo(a2, a3), pack_lo(a4, a5), pack_lo(a6, a7));
        }
        return;
    }
    __shared__ int warp_sums[32];
    const int bid = blockIdx.x - 12;
    const int lane = tid & 31, wid = tid >> 5;
    const int i = bid * 1024 + tid;
    int v = (i < N) ? (int)degree[i] : 0;
    int inc = v;
#pragma unroll
    for (int o = 1; o < 32; o <<= 1) {
        int t = __shfl_up_sync(0xffffffffu, inc, o);
        if (lane >= o) inc += t;
    }
    if (lane == 31) warp_sums[wid] = inc;
    __syncthreads();
    if (wid == 0) {
        int ws = warp_sums[lane];
#pragma unroll
        for (int o = 1; o < 32; o <<= 1) {
            int t = __shfl_up_sync(0xffffffffu, ws, o);
            if (lane >= o) ws += t;
        }
        warp_sums[lane] = ws;
    }
    __syncthreads();
    int excl = (wid > 0 ? warp_sums[wid - 1] : 0) + inc - v;
    if (i < N) { g_base[i] = excl; g_cursor[i] = 0; }
    if (tid == 1023) g_bsum[bid] = warp_sums[31];
}

// Kernel B: scan block sums (1 block, 64 threads, nb <= 64)
__global__ void scan2_kernel(int nb) {
    const int tid = threadIdx.x, lane = tid & 31, wid = tid >> 5;
    __shared__ int ws2[2];
    int v = (tid < nb) ? g_bsum[tid] : 0;
    int inc = v;
#pragma unroll
    for (int o = 1; o < 32; o <<= 1) {
        int t = __shfl_up_sync(0xffffffffu, inc, o);
        if (lane >= o) inc += t;
    }
    if (lane == 31) ws2[wid] = inc;
    __syncthreads();
    int excl = inc - v + (wid > 0 ? ws2[0] : 0);
    if (tid < nb) g_bsum[tid] = excl;
}

// Kernel C: CSR fill (adds block offset inline)
__global__ void fill_kernel(const int* __restrict__ esrc,
                            const int* __restrict__ edst, int E) {
    int e = blockIdx.x * blockDim.x + threadIdx.x;
    if (e >= E) return;
    int t = edst[e];
    int pos = g_base[t] + g_bsum[t >> 10] + atomicAdd(&g_cursor[t], 1);
    if (pos < MAXE) g_csr[pos] = esrc[e];
}

// ---------------------------------------------------------------------------
// Fused kernel: CSR-gather + LN(x) + LN(neighbor) -> split-bf16 mma GEMM1
//               -> GELU -> GEMM2 -> bias + residual.  2 CTAs/SM.
// Row-separable warp mapping: warps 0-3 own rows 0-31, warps 4-7 own rows
// 32-63. All barriers are 128-thread named barriers -> two free-running
// pipelines per CTA (4 per SM) that overlap each other's gather/MMA phases.
// ---------------------------------------------------------------------------
__global__ void __launch_bounds__(NTHREADS, 2)
fused_kernel(const float* __restrict__ x,
             const float* __restrict__ degree,
             const float* __restrict__ sn_g, const float* __restrict__ sn_b,
             const float* __restrict__ nn_g, const float* __restrict__ nn_b,
             const float* __restrict__ b1,  const float* __restrict__ b2,
             float* __restrict__ out, int N, int nrows) {
    extern __shared__ char sm[];
    const uint32_t smem_base = smem_u32(sm);
    char* Ahi = sm + SMEM_AHI;
    char* Alo = sm + SMEM_ALO;

    const int tid  = threadIdx.x;
    const int lane = tid & 31;
    const int warp = tid >> 5;
    const int grp  = warp >> 2;     // half-CTA group: 0 (rows 0-31) / 1 (rows 32-63)
    const int wm   = grp;           // M group
    const int wn   = warp & 3;      // N group
    const int row0 = blockIdx.x * MTILE;
    const int g    = lane >> 3;
    const int lr   = lane & 7;

    // ---------------- Stage 1: gather + LayerNorms -> A images --------------
    {
        const float4 g1  = *reinterpret_cast<const float4*>(sn_g + lane * 4);
        const float4 be1 = *reinterpret_cast<const float4*>(sn_b + lane * 4);
        const float4 g2  = *reinterpret_cast<const float4*>(nn_g + lane * 4);
        const float4 be2 = *reinterpret_cast<const float4*>(nn_b + lane * 4);
        const int k0 = lane * 4;
#pragma unroll
        for (int rr = 0; rr < 8; rr++) {
            const int r    = warp * 8 + rr;   // warps 0-3 -> rows 0-31 (grp 0)
            const int grow = row0 + r;
            if (grow < nrows) {
                // ---- LN(x) ----
                float4 xv = *reinterpret_cast<const float4*>(x + (size_t)grow * D + k0);
                float sum  = xv.x + xv.y + xv.z + xv.w;
                float sumq = xv.x * xv.x + xv.y * xv.y + xv.z * xv.z + xv.w * xv.w;
#pragma unroll
                for (int o = 16; o > 0; o >>= 1) {
                    sum  += __shfl_xor_sync(0xffffffffu, sum, o);
                    sumq += __shfl_xor_sync(0xffffffffu, sumq, o);
                }
                float mn   = sum * (1.0f / 128.0f);
                float rstd = rsqrtf(sumq * (1.0f / 128.0f) - mn * mn + 1e-5f);
                split_pair(Ahi, Alo, a_off(r, k0),     (xv.x - mn) * rstd * g1.x + be1.x,
                                                       (xv.y - mn) * rstd * g1.y + be1.y);
                split_pair(Ahi, Alo, a_off(r, k0 + 2), (xv.z - mn) * rstd * g1.z + be1.z,
                                                       (xv.w - mn) * rstd * g1.w + be1.w);

                // ---- CSR gather of neighbors (4-wide unroll, 2 accumulators)
                int node = grow, boff = 0;
                if (grow >= N) { node = grow - N; boff = N; }
                const float dgf = degree[node];
                const int   deg = (int)dgf;
                const float inv = 1.0f / fmaxf(dgf, 1.0f);
                const int   bs  = g_base[node] + g_bsum[node >> 10];
                float4 nva = make_float4(0.f, 0.f, 0.f, 0.f);
                float4 nvb = make_float4(0.f, 0.f, 0.f, 0.f);
                int j = 0;
                for (; j + 4 <= deg; j += 4) {
                    int s0 = g_csr[bs + j],     s1 = g_csr[bs + j + 1];
                    int s2 = g_csr[bs + j + 2], s3 = g_csr[bs + j + 3];
                    const float4 v0 = *reinterpret_cast<const float4*>(
                        x + ((size_t)(boff + s0)) * D + k0);
                    const float4 v1 = *reinterpret_cast<const float4*>(
                        x + ((size_t)(boff + s1)) * D + k0);
                    const float4 v2 = *reinterpret_cast<const float4*>(
                        x + ((size_t)(boff + s2)) * D + k0);
                    const float4 v3 = *reinterpret_cast<const float4*>(
                        x + ((size_t)(boff + s3)) * D + k0);
                    nva.x += v0.x + v1.x; nva.y += v0.y + v1.y;
                    nva.z += v0.z + v1.z; nva.w += v0.w + v1.w;
                    nvb.x += v2.x + v3.x; nvb.y += v2.y + v3.y;
                    nvb.z += v2.z + v3.z; nvb.w += v2.w + v3.w;
                }
                for (; j < deg; j++) {
                    int s0 = g_csr[bs + j];
                    const float4 v0 = *reinterpret_cast<const float4*>(
                        x + ((size_t)(boff + s0)) * D + k0);
                    nva.x += v0.x; nva.y += v0.y; nva.z += v0.z; nva.w += v0.w;
                }
                float4 nv;
                nv.x = (nva.x + nvb.x) * inv;
                nv.y = (nva.y + nvb.y) * inv;
                nv.z = (nva.z + nvb.z) * inv;
                nv.w = (nva.w + nvb.w) * inv;

                // ---- LN(neighbor) ----
                sum  = nv.x + nv.y + nv.z + nv.w;
                sumq = nv.x * nv.x + nv.y * nv.y + nv.z * nv.z + nv.w * nv.w;
#pragma unroll
                for (int o = 16; o > 0; o >>= 1) {
                    sum  += __shfl_xor_sync(0xffffffffu, sum, o);
                    sumq += __shfl_xor_sync(0xffffffffu, sumq, o);
                }
                mn   = sum * (1.0f / 128.0f);
                rstd = rsqrtf(sumq * (1.0f / 128.0f) - mn * mn + 1e-5f);
                split_pair(Ahi, Alo, a_off(r, 128 + k0),     (nv.x - mn) * rstd * g2.x + be2.x,
                                                             (nv.y - mn) * rstd * g2.y + be2.y);
                split_pair(Ahi, Alo, a_off(r, 128 + k0 + 2), (nv.z - mn) * rstd * g2.z + be2.z,
                                                             (nv.w - mn) * rstd * g2.w + be2.w);
            } else {
                split_pair(Ahi, Alo, a_off(r, k0),           0.f, 0.f);
                split_pair(Ahi, Alo, a_off(r, k0 + 2),       0.f, 0.f);
                split_pair(Ahi, Alo, a_off(r, 128 + k0),     0.f, 0.f);
                split_pair(Ahi, Alo, a_off(r, 128 + k0 + 2), 0.f, 0.f);
            }
        }
    }
    GROUP_BAR(grp);

    // ---------------- Stage 2: GEMM1 (32 x 256 x 256 per group) -------------
    float acc[2][8][4];
#pragma unroll
    for (int i = 0; i < 2; i++)
#pragma unroll
        for (int j = 0; j < 8; j++)
#pragma unroll
            for (int r = 0; r < 4; r++) acc[i][j][r] = 0.f;

#pragma unroll 2
    for (int ks = 0; ks < 16; ks++) {
        const int kabs = ks * 16;
        uint32_t ahi[2][4], alo[2][4];
#pragma unroll
        for (int ti = 0; ti < 2; ti++) {
            int row = wm * 32 + ti * 16 + (g & 1) * 8 + lr;
            uint32_t off = row * A_STRIDE + (((kabs >> 3) + (g >> 1)) << 4);
            ldsm4(ahi[ti], smem_base + SMEM_AHI + off);
            ldsm4(alo[ti], smem_base + SMEM_ALO + off);
        }
#pragma unroll
        for (int jj = 0; jj < 4; jj++) {
            const int fi = (ks * 16 + wn * 4 + jj) * 32 + lane;
            const uint4 fh = g_B1fh[fi];
            const uint4 fl = g_B1fl[fi];
#pragma unroll
            for (int ti = 0; ti < 2; ti++) {
                mma16816(acc[ti][2 * jj],     ahi[ti], fh.x, fh.y);
                mma16816(acc[ti][2 * jj],     ahi[ti], fl.x, fl.y);
                mma16816(acc[ti][2 * jj],     alo[ti], fh.x, fh.y);
                mma16816(acc[ti][2 * jj + 1], ahi[ti], fh.z, fh.w);
                mma16816(acc[ti][2 * jj + 1], ahi[ti], fl.z, fl.w);
                mma16816(acc[ti][2 * jj + 1], alo[ti], fh.z, fh.w);
            }
        }
    }

    // ---------------- Stage 3: bias + GELU -> A2 images ---------------------
    GROUP_BAR(grp);
#pragma unroll
    for (int tj = 0; tj < 8; tj++) {
        const int col = wn * 64 + tj * 8 + (lane & 3) * 2;
        const float2 bb = *reinterpret_cast<const float2*>(b1 + col);
#pragma unroll
        for (int ti = 0; ti < 2; ti++)
#pragma unroll
            for (int rp = 0; rp < 2; rp++) {
                int row = wm * 32 + ti * 16 + (lane >> 2) + rp * 8;
                float v0 = acc[ti][tj][rp * 2 + 0] + bb.x;
                float v1 = acc[ti][tj][rp * 2 + 1] + bb.y;
                v0 = 0.5f * v0 * (1.0f + erff(v0 * 0.70710678118654752f));
                v1 = 0.5f * v1 * (1.0f + erff(v1 * 0.70710678118654752f));
                split_pair(Ahi, Alo, a_off(row, col), v0, v1);
            }
    }
    GROUP_BAR(grp);

    // ---------------- Stage 4: GEMM2 (32 x 128 x 256 per group) -------------
    float c2[2][4][4];
#pragma unroll
    for (int i = 0; i < 2; i++)
#pragma unroll
        for (int j = 0; j < 4; j++)
#pragma unroll
            for (int r = 0; r < 4; r++) c2[i][j][r] = 0.f;

#pragma unroll 2
    for (int ks = 0; ks < 16; ks++) {
        const int kabs = ks * 16;
        uint32_t ahi[2][4], alo[2][4];
#pragma unroll
        for (int ti = 0; ti < 2; ti++) {
            int row = wm * 32 + ti * 16 + (g & 1) * 8 + lr;
            uint32_t off = row * A_STRIDE + (((kabs >> 3) + (g >> 1)) << 4);
            ldsm4(ahi[ti], smem_base + SMEM_AHI + off);
            ldsm4(alo[ti], smem_base + SMEM_ALO + off);
        }
#pragma unroll
        for (int jj = 0; jj < 2; jj++) {
            const int fi = (ks * 8 + wn * 2 + jj) * 32 + lane;
            const uint4 fh = g_B2fh[fi];
            const uint4 fl = g_B2fl[fi];
#pragma unroll
            for (int ti = 0; ti < 2; ti++) {
                mma16816(c2[ti][2 * jj],     ahi[ti], fh.x, fh.y);
                mma16816(c2[ti][2 * jj],     ahi[ti], fl.x, fl.y);
                mma16816(c2[ti][2 * jj],     alo[ti], fh.x, fh.y);
                mma16816(c2[ti][2 * jj + 1], ahi[ti], fh.z, fh.w);
                mma16816(c2[ti][2 * jj + 1], ahi[ti], fl.z, fl.w);
                mma16816(c2[ti][2 * jj + 1], alo[ti], fh.z, fh.w);
            }
        }
    }

    // ---------------- Stage 5: bias + residual + store ----------------------
#pragma unroll
    for (int tj = 0; tj < 4; tj++) {
        const int col = wn * 32 + tj * 8 + (lane & 3) * 2;
        const float2 bb = *reinterpret_cast<const float2*>(b2 + col);
#pragma unroll
        for (int ti = 0; ti < 2; ti++)
#pragma unroll
            for (int rp = 0; rp < 2; rp++) {
                int row  = wm * 32 + ti * 16 + (lane >> 2) + rp * 8;
                int grow = row0 + row;
                if (grow < nrows) {
                    const float2 xv = *reinterpret_cast<const float2*>(x + (size_t)grow * D + col);
                    float2 o;
                    o.x = xv.x + c2[ti][tj][rp * 2 + 0] + bb.x;
                    o.y = xv.y + c2[ti][tj][rp * 2 + 1] + bb.y;
                    *reinterpret_cast<float2*>(out + (size_t)grow * D + col) = o;
                }
            }
    }
}

// ---------------------------------------------------------------------------
extern "C" void kernel_launch(void* const* d_in, const int* in_sizes, int n_in,
                              void* d_out, int out_size) {
    const float* x      = (const float*)d_in[0];
    const int*   esrc   = (const int*)  d_in[1];
    const int*   edst   = (const int*)  d_in[2];
    const float* degree = (const float*)d_in[3];
    const float* sn_g   = (const float*)d_in[4];
    const float* sn_b   = (const float*)d_in[5];
    const float* nn_g   = (const float*)d_in[6];
    const float* nn_b   = (const float*)d_in[7];
    const float* W1     = (const float*)d_in[8];
    const float* b1     = (const float*)d_in[9];
    const float* W2     = (const float*)d_in[10];
    const float* b2     = (const float*)d_in[11];

    const int E     = in_sizes[1];
    const int nrows = in_sizes[0] / D;   // B*N
    const int N     = in_sizes[3];
    const int nb    = (N + 1023) / 1024;

    prep_scan_kernel<<<12 + nb, 1024>>>(W1, W2, degree, N);
    scan2_kernel<<<1, 64>>>(nb);
    fill_kernel<<<(E + 255) / 256, 256>>>(esrc, edst, E);

    cudaFuncSetAttribute(fused_kernel, cudaFuncAttributeMaxDynamicSharedMemorySize, SMEM_TOTAL);
    fused_kernel<<<(nrows + MTILE - 1) / MTILE, NTHREADS, SMEM_TOTAL>>>(
        x, degree, sn_g, sn_b, nn_g, nn_b, b1, b2, (float*)d_out, N, nrows);
}

// round 15
// speedup vs baseline: 1.1311x; 1.1132x over previous
#include <cuda_runtime.h>
#include <cuda_bf16.h>
#include <cstdint>
#include <stdint.h>
#include <math.h>

#define D      128
#define TWO_D  256
#define MTILE  32
#define NTHREADS 256
#define MAXN   50000
#define MAXE   800000

// A image: 32 rows x 256 bf16, row stride 528 bytes (conflict-free LDSM)
#define A_STRIDE 528
#define A_IMG    (32 * A_STRIDE)      // 16896
#define SMEM_AHI 0
#define SMEM_ALO A_IMG
#define SMEM_TOTAL (2 * A_IMG)        // 33792 -> 3 CTAs/SM (smem-wise up to 6)

// ---------------------------------------------------------------------------
// Device globals
// ---------------------------------------------------------------------------
__device__ int   g_base[MAXN + 1];    // per-block-local exclusive scan
__device__ int   g_cursor[MAXN];
__device__ int   g_csr[MAXE];
__device__ int   g_bsum[64];          // block offsets (exclusive)
// Pre-computed mma.sync B fragments (per-lane register images), hi/lo terms.
__device__ uint4 g_B1fh[8192];
__device__ uint4 g_B1fl[8192];
__device__ uint4 g_B2fh[4096];
__device__ uint4 g_B2fl[4096];

// ---------------------------------------------------------------------------
// helpers
// ---------------------------------------------------------------------------
__device__ __forceinline__ uint32_t smem_u32(const void* p) {
    uint32_t a;
    asm("{ .reg .u64 t; cvta.to.shared.u64 t, %1; cvt.u32.u64 %0, t; }" : "=r"(a) : "l"(p));
    return a;
}
__device__ __forceinline__ void ldsm4(uint32_t* r, uint32_t addr) {
    asm volatile("ldmatrix.sync.aligned.m8n8.x4.shared.b16 {%0,%1,%2,%3}, [%4];"
                 : "=r"(r[0]), "=r"(r[1]), "=r"(r[2]), "=r"(r[3]) : "r"(addr));
}
__device__ __forceinline__ void mma16816(float* d, const uint32_t* a, uint32_t b0, uint32_t b1) {
    asm volatile("mma.sync.aligned.m16n8k16.row.col.f32.bf16.bf16.f32 "
                 "{%0,%1,%2,%3}, {%4,%5,%6,%7}, {%8,%9}, {%0,%1,%2,%3};"
                 : "+f"(d[0]), "+f"(d[1]), "+f"(d[2]), "+f"(d[3])
                 : "r"(a[0]), "r"(a[1]), "r"(a[2]), "r"(a[3]), "r"(b0), "r"(b1));
}
__device__ __forceinline__ int a_off(int row, int k) {
    return row * A_STRIDE + ((k >> 3) << 4) + ((k & 7) << 1);
}
__device__ __forceinline__ void split_pair(char* hi_base, char* lo_base, int off,
                                           float v0, float v1) {
    __nv_bfloat16 h0 = __float2bfloat16(v0);
    __nv_bfloat16 h1 = __float2bfloat16(v1);
    __nv_bfloat16 l0 = __float2bfloat16(v0 - __bfloat162float(h0));
    __nv_bfloat16 l1 = __float2bfloat16(v1 - __bfloat162float(h1));
    *reinterpret_cast<__nv_bfloat162*>(hi_base + off) = __halves2bfloat162(h0, h1);
    *reinterpret_cast<__nv_bfloat162*>(lo_base + off) = __halves2bfloat162(l0, l1);
}
__device__ __forceinline__ uint32_t pack_hi(float a, float b) {
    __nv_bfloat162 v = __halves2bfloat162(__float2bfloat16(a), __float2bfloat16(b));
    return *reinterpret_cast<uint32_t*>(&v);
}
__device__ __forceinline__ uint32_t pack_lo(float a, float b) {
    __nv_bfloat16 ha = __float2bfloat16(a), hb = __float2bfloat16(b);
    __nv_bfloat162 v = __halves2bfloat162(__float2bfloat16(a - __bfloat162float(ha)),
                                          __float2bfloat16(b - __bfloat162float(hb)));
    return *reinterpret_cast<uint32_t*>(&v);
}

// ---------------------------------------------------------------------------
// Kernel A (merged): blocks [0,12) -> weight fragment prep
//                    blocks [12, 12+nb) -> per-block scan of degree
// ---------------------------------------------------------------------------
__global__ void prep_scan_kernel(const float* __restrict__ W1,
                                 const float* __restrict__ W2,
                                 const float* __restrict__ degree, int N) {
    const int tid = threadIdx.x;
    if (blockIdx.x < 12) {
        int idx = blockIdx.x * 1024 + tid;
        if (idx < 8192) {
            int lane = idx & 31, ng = (idx >> 5) & 15, ks = idx >> 9;
            int n0 = ng * 16 + (lane >> 2);
            int kb = ks * 16 + (lane & 3) * 2;
            float a0 = W1[(size_t)(kb)     * 256 + n0], a1 = W1[(size_t)(kb + 1) * 256 + n0];
            float a2 = W1[(size_t)(kb + 8) * 256 + n0], a3 = W1[(size_t)(kb + 9) * 256 + n0];
            float a4 = W1[(size_t)(kb)     * 256 + n0 + 8], a5 = W1[(size_t)(kb + 1) * 256 + n0 + 8];
            float a6 = W1[(size_t)(kb + 8) * 256 + n0 + 8], a7 = W1[(size_t)(kb + 9) * 256 + n0 + 8];
            g_B1fh[idx] = make_uint4(pack_hi(a0, a1), pack_hi(a2, a3), pack_hi(a4, a5), pack_hi(a6, a7));
            g_B1fl[idx] = make_uint4(pack_lo(a0, a1), pack_lo(a2, a3), pack_lo(a4, a5), pack_lo(a6, a7));
        } else if (idx < 12288) {
            int i2 = idx - 8192;
            int lane = i2 & 31, ng = (i2 >> 5) & 7, ks = i2 >> 8;
            int n0 = ng * 16 + (lane >> 2);
            int kb = ks * 16 + (lane & 3) * 2;
            float a0 = W2[(size_t)(kb)     * 128 + n0], a1 = W2[(size_t)(kb + 1) * 128 + n0];
            float a2 = W2[(size_t)(kb + 8) * 128 + n0], a3 = W2[(size_t)(kb + 9) * 128 + n0];
            float a4 = W2[(size_t)(kb)     * 128 + n0 + 8], a5 = W2[(size_t)(kb + 1) * 128 + n0 + 8];
            float a6 = W2[(size_t)(kb + 8) * 128 + n0 + 8], a7 = W2[(size_t)(kb + 9) * 128 + n0 + 8];
            g_B2fh[i2] = make_uint4(pack_hi(a0, a1), pack_hi(a2, a3), pack_hi(a4, a5), pack_hi(a6, a7));
            g_B2fl[i2] = make_uint4(pack_lo(a0, a1), pack_lo(a2, a3), pack_lo(a4, a5), pack_lo(a6, a7));
        }
        return;
    }
    __shared__ int warp_sums[32];
    const int bid = blockIdx.x - 12;
    const int lane = tid & 31, wid = tid >> 5;
    const int i = bid * 1024 + tid;
    int v = (i < N) ? (int)degree[i] : 0;
    int inc = v;
#pragma unroll
    for (int o = 1; o < 32; o <<= 1) {
        int t = __shfl_up_sync(0xffffffffu, inc, o);
        if (lane >= o) inc += t;
    }
    if (lane == 31) warp_sums[wid] = inc;
    __syncthreads();
    if (wid == 0) {
        int ws = warp_sums[lane];
#pragma unroll
        for (int o = 1; o < 32; o <<= 1) {
            int t = __shfl_up_sync(0xffffffffu, ws, o);
            if (lane >= o) ws += t;
        }
        warp_sums[lane] = ws;
    }
    __syncthreads();
    int excl = (wid > 0 ? warp_sums[wid - 1] : 0) + inc - v;
    if (i < N) { g_base[i] = excl; g_cursor[i] = 0; }
    if (tid == 1023) g_bsum[bid] = warp_sums[31];
}

// Kernel B: scan block sums (1 block, 64 threads, nb <= 64)
__global__ void scan2_kernel(int nb) {
    const int tid = threadIdx.x, lane = tid & 31, wid = tid >> 5;
    __shared__ int ws2[2];
    int v = (tid < nb) ? g_bsum[tid] : 0;
    int inc = v;
#pragma unroll
    for (int o = 1; o < 32; o <<= 1) {
        int t = __shfl_up_sync(0xffffffffu, inc, o);
        if (lane >= o) inc += t;
    }
    if (lane == 31) ws2[wid] = inc;
    __syncthreads();
    int excl = inc - v + (wid > 0 ? ws2[0] : 0);
    if (tid < nb) g_bsum[tid] = excl;
}

// Kernel C: CSR fill (adds block offset inline)
__global__ void fill_kernel(const int* __restrict__ esrc,
                            const int* __restrict__ edst, int E) {
    int e = blockIdx.x * blockDim.x + threadIdx.x;
    if (e >= E) return;
    int t = edst[e];
    int pos = g_base[t] + g_bsum[t >> 10] + atomicAdd(&g_cursor[t], 1);
    if (pos < MAXE) g_csr[pos] = esrc[e];
}

// ---------------------------------------------------------------------------
// Fused kernel: CSR-gather + LN(x) + LN(neighbor) -> split-bf16 mma GEMM1
//               -> GELU -> GEMM2 -> bias + residual.
// 32 rows/CTA, 8 warps ALL in N (warp tile 32x32 GEMM1, 32x16 GEMM2).
// Small tiles -> ~80 regs -> 3 CTAs/SM (24 warps) for latency hiding.
// ---------------------------------------------------------------------------
__global__ void __launch_bounds__(NTHREADS, 3)
fused_kernel(const float* __restrict__ x,
             const float* __restrict__ degree,
             const float* __restrict__ sn_g, const float* __restrict__ sn_b,
             const float* __restrict__ nn_g, const float* __restrict__ nn_b,
             const float* __restrict__ b1,  const float* __restrict__ b2,
             float* __restrict__ out, int N, int nrows) {
    extern __shared__ char sm[];
    const uint32_t smem_base = smem_u32(sm);
    char* Ahi = sm + SMEM_AHI;
    char* Alo = sm + SMEM_ALO;

    const int tid  = threadIdx.x;
    const int lane = tid & 31;
    const int warp = tid >> 5;      // 0..7 = N group
    const int wn   = warp;
    const int row0 = blockIdx.x * MTILE;
    const int g    = lane >> 3;
    const int lr   = lane & 7;

    // ---------------- Stage 1: gather + LayerNorms -> A images --------------
    {
        const float4 g1  = *reinterpret_cast<const float4*>(sn_g + lane * 4);
        const float4 be1 = *reinterpret_cast<const float4*>(sn_b + lane * 4);
        const float4 g2  = *reinterpret_cast<const float4*>(nn_g + lane * 4);
        const float4 be2 = *reinterpret_cast<const float4*>(nn_b + lane * 4);
        const int k0 = lane * 4;
#pragma unroll
        for (int rr = 0; rr < 4; rr++) {
            const int r    = warp * 4 + rr;   // 0..31
            const int grow = row0 + r;
            if (grow < nrows) {
                // ---- LN(x) ----
                float4 xv = *reinterpret_cast<const float4*>(x + (size_t)grow * D + k0);
                float sum  = xv.x + xv.y + xv.z + xv.w;
                float sumq = xv.x * xv.x + xv.y * xv.y + xv.z * xv.z + xv.w * xv.w;
#pragma unroll
                for (int o = 16; o > 0; o >>= 1) {
                    sum  += __shfl_xor_sync(0xffffffffu, sum, o);
                    sumq += __shfl_xor_sync(0xffffffffu, sumq, o);
                }
                float mn   = sum * (1.0f / 128.0f);
                float rstd = rsqrtf(sumq * (1.0f / 128.0f) - mn * mn + 1e-5f);
                split_pair(Ahi, Alo, a_off(r, k0),     (xv.x - mn) * rstd * g1.x + be1.x,
                                                       (xv.y - mn) * rstd * g1.y + be1.y);
                split_pair(Ahi, Alo, a_off(r, k0 + 2), (xv.z - mn) * rstd * g1.z + be1.z,
                                                       (xv.w - mn) * rstd * g1.w + be1.w);

                // ---- CSR gather of neighbors (4-wide unroll, 2 accumulators)
                int node = grow, boff = 0;
                if (grow >= N) { node = grow - N; boff = N; }
                const float dgf = degree[node];
                const int   deg = (int)dgf;
                const float inv = 1.0f / fmaxf(dgf, 1.0f);
                const int   bs  = g_base[node] + g_bsum[node >> 10];
                float4 nva = make_float4(0.f, 0.f, 0.f, 0.f);
                float4 nvb = make_float4(0.f, 0.f, 0.f, 0.f);
                int j = 0;
                for (; j + 4 <= deg; j += 4) {
                    int s0 = g_csr[bs + j],     s1 = g_csr[bs + j + 1];
                    int s2 = g_csr[bs + j + 2], s3 = g_csr[bs + j + 3];
                    const float4 v0 = *reinterpret_cast<const float4*>(
                        x + ((size_t)(boff + s0)) * D + k0);
                    const float4 v1 = *reinterpret_cast<const float4*>(
                        x + ((size_t)(boff + s1)) * D + k0);
                    const float4 v2 = *reinterpret_cast<const float4*>(
                        x + ((size_t)(boff + s2)) * D + k0);
                    const float4 v3 = *reinterpret_cast<const float4*>(
                        x + ((size_t)(boff + s3)) * D + k0);
                    nva.x += v0.x + v1.x; nva.y += v0.y + v1.y;
                    nva.z += v0.z + v1.z; nva.w += v0.w + v1.w;
                    nvb.x += v2.x + v3.x; nvb.y += v2.y + v3.y;
                    nvb.z += v2.z + v3.z; nvb.w += v2.w + v3.w;
                }
                for (; j < deg; j++) {
                    int s0 = g_csr[bs + j];
                    const float4 v0 = *reinterpret_cast<const float4*>(
                        x + ((size_t)(boff + s0)) * D + k0);
                    nva.x += v0.x; nva.y += v0.y; nva.z += v0.z; nva.w += v0.w;
                }
                float4 nv;
                nv.x = (nva.x + nvb.x) * inv;
                nv.y = (nva.y + nvb.y) * inv;
                nv.z = (nva.z + nvb.z) * inv;
                nv.w = (nva.w + nvb.w) * inv;

                // ---- LN(neighbor) ----
                sum  = nv.x + nv.y + nv.z + nv.w;
                sumq = nv.x * nv.x + nv.y * nv.y + nv.z * nv.z + nv.w * nv.w;
#pragma unroll
                for (int o = 16; o > 0; o >>= 1) {
                    sum  += __shfl_xor_sync(0xffffffffu, sum, o);
                    sumq += __shfl_xor_sync(0xffffffffu, sumq, o);
                }
                mn   = sum * (1.0f / 128.0f);
                rstd = rsqrtf(sumq * (1.0f / 128.0f) - mn * mn + 1e-5f);
                split_pair(Ahi, Alo, a_off(r, 128 + k0),     (nv.x - mn) * rstd * g2.x + be2.x,
                                                             (nv.y - mn) * rstd * g2.y + be2.y);
                split_pair(Ahi, Alo, a_off(r, 128 + k0 + 2), (nv.z - mn) * rstd * g2.z + be2.z,
                                                             (nv.w - mn) * rstd * g2.w + be2.w);
            } else {
                split_pair(Ahi, Alo, a_off(r, k0),           0.f, 0.f);
                split_pair(Ahi, Alo, a_off(r, k0 + 2),       0.f, 0.f);
                split_pair(Ahi, Alo, a_off(r, 128 + k0),     0.f, 0.f);
                split_pair(Ahi, Alo, a_off(r, 128 + k0 + 2), 0.f, 0.f);
            }
        }
    }
    __syncthreads();

    // ---------------- Stage 2: GEMM1 (32 x 32-per-warp x 256, 3 terms) ------
    float acc[2][4][4];     // [ti][col-tile of 8][4]  = 32 regs
#pragma unroll
    for (int i = 0; i < 2; i++)
#pragma unroll
        for (int j = 0; j < 4; j++)
#pragma unroll
            for (int r = 0; r < 4; r++) acc[i][j][r] = 0.f;

#pragma unroll 2
    for (int ks = 0; ks < 16; ks++) {
        const int kabs = ks * 16;
        uint32_t ahi[2][4], alo[2][4];
#pragma unroll
        for (int ti = 0; ti < 2; ti++) {
            int row = ti * 16 + (g & 1) * 8 + lr;
            uint32_t off = row * A_STRIDE + (((kabs >> 3) + (g >> 1)) << 4);
            ldsm4(ahi[ti], smem_base + SMEM_AHI + off);
            ldsm4(alo[ti], smem_base + SMEM_ALO + off);
        }
#pragma unroll
        for (int jj = 0; jj < 2; jj++) {
            const int fi = (ks * 16 + wn * 2 + jj) * 32 + lane;
            const uint4 fh = g_B1fh[fi];
            const uint4 fl = g_B1fl[fi];
#pragma unroll
            for (int ti = 0; ti < 2; ti++) {
                mma16816(acc[ti][2 * jj],     ahi[ti], fh.x, fh.y);
                mma16816(acc[ti][2 * jj],     ahi[ti], fl.x, fl.y);
                mma16816(acc[ti][2 * jj],     alo[ti], fh.x, fh.y);
                mma16816(acc[ti][2 * jj + 1], ahi[ti], fh.z, fh.w);
                mma16816(acc[ti][2 * jj + 1], ahi[ti], fl.z, fl.w);
                mma16816(acc[ti][2 * jj + 1], alo[ti], fh.z, fh.w);
            }
        }
    }

    // ---------------- Stage 3: bias + GELU -> A2 images ---------------------
    __syncthreads();
#pragma unroll
    for (int tj = 0; tj < 4; tj++) {
        const int col = wn * 32 + tj * 8 + (lane & 3) * 2;
        const float2 bb = *reinterpret_cast<const float2*>(b1 + col);
#pragma unroll
        for (int ti = 0; ti < 2; ti++)
#pragma unroll
            for (int rp = 0; rp < 2; rp++) {
                int row = ti * 16 + (lane >> 2) + rp * 8;
                float v0 = acc[ti][tj][rp * 2 + 0] + bb.x;
                float v1 = acc[ti][tj][rp * 2 + 1] + bb.y;
                v0 = 0.5f * v0 * (1.0f + erff(v0 * 0.70710678118654752f));
                v1 = 0.5f * v1 * (1.0f + erff(v1 * 0.70710678118654752f));
                split_pair(Ahi, Alo, a_off(row, col), v0, v1);
            }
    }
    __syncthreads();

    // ---------------- Stage 4: GEMM2 (32 x 16-per-warp x 256, 3 terms) ------
    float c2[2][2][4];      // 16 regs
#pragma unroll
    for (int i = 0; i < 2; i++)
#pragma unroll
        for (int j = 0; j < 2; j++)
#pragma unroll
            for (int r = 0; r < 4; r++) c2[i][j][r] = 0.f;

#pragma unroll 2
    for (int ks = 0; ks < 16; ks++) {
        const int kabs = ks * 16;
        uint32_t ahi[2][4], alo[2][4];
#pragma unroll
        for (int ti = 0; ti < 2; ti++) {
            int row = ti * 16 + (g & 1) * 8 + lr;
            uint32_t off = row * A_STRIDE + (((kabs >> 3) + (g >> 1)) << 4);
            ldsm4(ahi[ti], smem_base + SMEM_AHI + off);
            ldsm4(alo[ti], smem_base + SMEM_ALO + off);
        }
        {
            const int fi = (ks * 8 + wn) * 32 + lane;
            const uint4 fh = g_B2fh[fi];
            const uint4 fl = g_B2fl[fi];
#pragma unroll
            for (int ti = 0; ti < 2; ti++) {
                mma16816(c2[ti][0], ahi[ti], fh.x, fh.y);
                mma16816(c2[ti][0], ahi[ti], fl.x, fl.y);
                mma16816(c2[ti][0], alo[ti], fh.x, fh.y);
                mma16816(c2[ti][1], ahi[ti], fh.z, fh.w);
                mma16816(c2[ti][1], ahi[ti], fl.z, fl.w);
                mma16816(c2[ti][1], alo[ti], fh.z, fh.w);
            }
        }
    }

    // ---------------- Stage 5: bias + residual + store ----------------------
#pragma unroll
    for (int tj = 0; tj < 2; tj++) {
        const int col = wn * 16 + tj * 8 + (lane & 3) * 2;
        const float2 bb = *reinterpret_cast<const float2*>(b2 + col);
#pragma unroll
        for (int ti = 0; ti < 2; ti++)
#pragma unroll
            for (int rp = 0; rp < 2; rp++) {
                int row  = ti * 16 + (lane >> 2) + rp * 8;
                int grow = row0 + row;
                if (grow < nrows) {
                    const float2 xv = *reinterpret_cast<const float2*>(x + (size_t)grow * D + col);
                    float2 o;
                    o.x = xv.x + c2[ti][tj][rp * 2 + 0] + bb.x;
                    o.y = xv.y + c2[ti][tj][rp * 2 + 1] + bb.y;
                    *reinterpret_cast<float2*>(out + (size_t)grow * D + col) = o;
                }
            }
    }
}

// ---------------------------------------------------------------------------
extern "C" void kernel_launch(void* const* d_in, const int* in_sizes, int n_in,
                              void* d_out, int out_size) {
    const float* x      = (const float*)d_in[0];
    const int*   esrc   = (const int*)  d_in[1];
    const int*   edst   = (const int*)  d_in[2];
    const float* degree = (const float*)d_in[3];
    const float* sn_g   = (const float*)d_in[4];
    const float* sn_b   = (const float*)d_in[5];
    const float* nn_g   = (const float*)d_in[6];
    const float* nn_b   = (const float*)d_in[7];
    const float* W1     = (const float*)d_in[8];
    const float* b1     = (const float*)d_in[9];
    const float* W2     = (const float*)d_in[10];
    const float* b2     = (const float*)d_in[11];

    const int E     = in_sizes[1];
    const int nrows = in_sizes[0] / D;   // B*N
    const int N     = in_sizes[3];
    const int nb    = (N + 1023) / 1024;

    prep_scan_kernel<<<12 + nb, 1024>>>(W1, W2, degree, N);
    scan2_kernel<<<1, 64>>>(nb);
    fill_kernel<<<(E + 255) / 256, 256>>>(esrc, edst, E);

    cudaFuncSetAttribute(fused_kernel, cudaFuncAttributeMaxDynamicSharedMemorySize, SMEM_TOTAL);
    fused_kernel<<<(nrows + MTILE - 1) / MTILE, NTHREADS, SMEM_TOTAL>>>(
        x, degree, sn_g, sn_b, nn_g, nn_b, b1, b2, (float*)d_out, N, nrows);
}